// round 13
// baseline (speedup 1.0000x reference)
#include <cuda_runtime.h>
#include <cuda_bf16.h>

#define NUM_BINS    15
#define NUM_CLASSES 19
#define HW          (512 * 512)
#define BATCH       8

// Four pixels per thread (float4 per class), 128-thread blocks.
// launch_bounds(128,4) caps regs at 128 -> 4 blocks = 16 warps/SM with the
// same bytes-in-flight as the float2 version (16*19*512B = 155KB) but HALF
// the instructions per byte. Warp loads 32 consecutive float4 = 512B burst.
__global__ __launch_bounds__(128, 4)
void calib_kernel(const float* __restrict__ logits,
                  const float* __restrict__ val_freqs,
                  float* __restrict__ out)
{
    __shared__ float sfreq[NUM_CLASSES * NUM_BINS];  // 285 floats
    for (int i = threadIdx.x; i < NUM_CLASSES * NUM_BINS; i += blockDim.x)
        sfreq[i] = val_freqs[i];
    __syncthreads();

    const int s4 = blockIdx.x * blockDim.x + threadIdx.x;  // float4 index in image
    const int b  = blockIdx.y;

    const float4* __restrict__ in4 =
        (const float4*)(logits + (long long)b * (NUM_CLASSES * HW)) + s4;
    float4* __restrict__ out4 =
        (float4*)(out + (long long)b * (NUM_CLASSES * HW)) + s4;
    const int cstride4 = HW / 4;   // class stride in float4 units

    // ---- load all 19 classes (front-batched, high MLP, streaming) ----
    float4 v[NUM_CLASSES];
    #pragma unroll
    for (int c = 0; c < NUM_CLASSES; c++)
        v[c] = __ldcs(in4 + c * cstride4);

    // ---- per-lane max over classes ----
    float4 mx = v[0];
    #pragma unroll
    for (int c = 1; c < NUM_CLASSES; c++) {
        mx.x = fmaxf(mx.x, v[c].x);
        mx.y = fmaxf(mx.y, v[c].y);
        mx.z = fmaxf(mx.z, v[c].z);
        mx.w = fmaxf(mx.w, v[c].w);
    }

    // ---- exp(x - max), sum ----
    float4 sum = make_float4(0.f, 0.f, 0.f, 0.f);
    #pragma unroll
    for (int c = 0; c < NUM_CLASSES; c++) {
        v[c].x = expf(v[c].x - mx.x);  sum.x += v[c].x;
        v[c].y = expf(v[c].y - mx.y);  sum.y += v[c].y;
        v[c].z = expf(v[c].z - mx.z);  sum.z += v[c].z;
        v[c].w = expf(v[c].w - mx.w);  sum.w += v[c].w;
    }
    const float scx = (float)NUM_BINS / sum.x;   // bin = floor(e_c * 15 / sum)
    const float scy = (float)NUM_BINS / sum.y;
    const float scz = (float)NUM_BINS / sum.z;
    const float scw = (float)NUM_BINS / sum.w;

    // ---- bin + table gather + class-sum (cal overwrites v in place) ----
    float4 csum = make_float4(0.f, 0.f, 0.f, 0.f);
    #pragma unroll
    for (int c = 0; c < NUM_CLASSES; c++) {
        const float* f = sfreq + c * NUM_BINS;
        int bx = min((int)(v[c].x * scx), NUM_BINS - 1);
        int by = min((int)(v[c].y * scy), NUM_BINS - 1);
        int bz = min((int)(v[c].z * scz), NUM_BINS - 1);
        int bw = min((int)(v[c].w * scw), NUM_BINS - 1);
        v[c].x = f[bx];  csum.x += v[c].x;
        v[c].y = f[by];  csum.y += v[c].y;
        v[c].z = f[bz];  csum.z += v[c].z;
        v[c].w = f[bw];  csum.w += v[c].w;
    }

    // ---- normalize (guard s==0 -> 1, matching reference) ----
    csum.x = (csum.x == 0.f) ? 1.f : csum.x;
    csum.y = (csum.y == 0.f) ? 1.f : csum.y;
    csum.z = (csum.z == 0.f) ? 1.f : csum.z;
    csum.w = (csum.w == 0.f) ? 1.f : csum.w;
    const float ix = 1.0f / csum.x;
    const float iy = 1.0f / csum.y;
    const float iz = 1.0f / csum.z;
    const float iw = 1.0f / csum.w;

    // ---- store (streaming) ----
    #pragma unroll
    for (int c = 0; c < NUM_CLASSES; c++) {
        float4 o;
        o.x = v[c].x * ix;
        o.y = v[c].y * iy;
        o.z = v[c].z * iz;
        o.w = v[c].w * iw;
        __stcs(out4 + c * cstride4, o);
    }
}

extern "C" void kernel_launch(void* const* d_in, const int* in_sizes, int n_in,
                              void* d_out, int out_size)
{
    const float* logits    = (const float*)d_in[0];  // [8,19,512,512] f32
    const float* val_freqs = (const float*)d_in[1];  // [19,15] f32
    float* out = (float*)d_out;

    dim3 grid((HW / 4) / 128, BATCH);   // (512, 8)
    calib_kernel<<<grid, 128>>>(logits, val_freqs, out);
}

// round 15
// speedup vs baseline: 1.0537x; 1.0537x over previous
#include <cuda_runtime.h>
#include <cuda_bf16.h>

#define NUM_BINS    15
#define NUM_CLASSES 19
#define HW          (512 * 512)
#define BATCH       8

// Two pixels per thread (float2 per class), 32 warps/SM (best measured point).
// exp(x-mx) computed as exp2f(fma(x, log2e, -mx*log2e)) -> FFMA + MUFU.EX2,
// ~5x fewer instructions than accurate expf; shrinks the per-warp compute
// phase so warps return to the memory phase sooner.
__global__ __launch_bounds__(256, 4)
void calib_kernel(const float* __restrict__ logits,
                  const float* __restrict__ val_freqs,
                  float* __restrict__ out)
{
    __shared__ float sfreq[NUM_CLASSES * NUM_BINS];  // 285 floats
    for (int i = threadIdx.x; i < NUM_CLASSES * NUM_BINS; i += blockDim.x)
        sfreq[i] = val_freqs[i];
    __syncthreads();

    const int s2 = blockIdx.x * blockDim.x + threadIdx.x;  // float2 index in image
    const int b  = blockIdx.y;

    const float2* __restrict__ in2  =
        (const float2*)(logits + (long long)b * (NUM_CLASSES * HW)) + s2;
    float2* __restrict__ out2 =
        (float2*)(out + (long long)b * (NUM_CLASSES * HW)) + s2;
    const int cstride2 = HW / 2;   // class stride in float2 units

    // ---- load all 19 classes (front-batched, high MLP, streaming) ----
    float2 v[NUM_CLASSES];
    #pragma unroll
    for (int c = 0; c < NUM_CLASSES; c++)
        v[c] = __ldcs(in2 + c * cstride2);

    // ---- per-lane max over classes ----
    float mxx = v[0].x, mxy = v[0].y;
    #pragma unroll
    for (int c = 1; c < NUM_CLASSES; c++) {
        mxx = fmaxf(mxx, v[c].x);
        mxy = fmaxf(mxy, v[c].y);
    }

    // ---- exp(x - max) via exp2 (FFMA + MUFU.EX2), sum ----
    const float L2E = 1.4426950408889634f;
    const float nx = -mxx * L2E;
    const float ny = -mxy * L2E;
    float sx = 0.f, sy = 0.f;
    #pragma unroll
    for (int c = 0; c < NUM_CLASSES; c++) {
        v[c].x = exp2f(fmaf(v[c].x, L2E, nx));  sx += v[c].x;
        v[c].y = exp2f(fmaf(v[c].y, L2E, ny));  sy += v[c].y;
    }
    const float scx = (float)NUM_BINS / sx;   // bin = floor(e_c * 15 / sum)
    const float scy = (float)NUM_BINS / sy;

    // ---- bin + table gather + class-sum (cal overwrites v in place) ----
    float cx = 0.f, cy = 0.f;
    #pragma unroll
    for (int c = 0; c < NUM_CLASSES; c++) {
        const float* f = sfreq + c * NUM_BINS;
        int bx = min((int)(v[c].x * scx), NUM_BINS - 1);
        int by = min((int)(v[c].y * scy), NUM_BINS - 1);
        v[c].x = f[bx];  cx += v[c].x;
        v[c].y = f[by];  cy += v[c].y;
    }

    // ---- normalize (guard s==0 -> 1, matching reference) ----
    cx = (cx == 0.f) ? 1.f : cx;
    cy = (cy == 0.f) ? 1.f : cy;
    const float ix = 1.0f / cx;
    const float iy = 1.0f / cy;

    // ---- store (streaming) ----
    #pragma unroll
    for (int c = 0; c < NUM_CLASSES; c++) {
        float2 o;
        o.x = v[c].x * ix;
        o.y = v[c].y * iy;
        __stcs(out2 + c * cstride2, o);
    }
}

extern "C" void kernel_launch(void* const* d_in, const int* in_sizes, int n_in,
                              void* d_out, int out_size)
{
    const float* logits    = (const float*)d_in[0];  // [8,19,512,512] f32
    const float* val_freqs = (const float*)d_in[1];  // [19,15] f32
    float* out = (float*)d_out;

    dim3 grid((HW / 2) / 256, BATCH);   // (512, 8)
    calib_kernel<<<grid, 256>>>(logits, val_freqs, out);
}